// round 13
// baseline (speedup 1.0000x reference)
#include <cuda_runtime.h>
#include <cstdint>

// Problem constants
#define N_PTS 131072
#define DIM   64
#define KCENT 1024

typedef unsigned long long u64;

// Scratch (device globals — no allocation allowed)
__device__ float g_csq[KCENT];
__device__ int   g_ind[N_PTS];
__device__ int   g_counts[KCENT];
__device__ float g_csum[KCENT * DIM];   // [k][d] segment sums of x
__device__ float g_cnew[KCENT * DIM];   // [k][d] updated codebook
__device__ float g_loss;
__device__ unsigned int g_done;

// ---- packed f32x2 helpers (Blackwell 2-wide fp32 datapath) ------------------
__device__ __forceinline__ u64 ffma2(u64 a, u64 b, u64 c) {
    u64 d;
    asm("fma.rn.f32x2 %0, %1, %2, %3;" : "=l"(d) : "l"(a), "l"(b), "l"(c));
    return d;
}
__device__ __forceinline__ u64 pack2(float lo, float hi) {
    u64 d; asm("mov.b64 %0, {%1, %2};" : "=l"(d) : "f"(lo), "f"(hi)); return d;
}
__device__ __forceinline__ void unpack2(u64 v, float& lo, float& hi) {
    asm("mov.b64 {%0, %1}, %2;" : "=f"(lo), "=f"(hi) : "l"(v));
}

// ---------------------------------------------------------------------------
// Fused prep: zero csum/counts/loss/done + csq[k] = sum_d C[d][k]^2
// ---------------------------------------------------------------------------
__global__ void prep_kernel(const float* __restrict__ C) {
    int i = blockIdx.x * blockDim.x + threadIdx.x;
    g_csum[i] = 0.0f;
    if (i < KCENT) {
        g_counts[i] = 0;
        float s = 0.0f;
        #pragma unroll
        for (int d = 0; d < DIM; d++) {
            float c = C[d * KCENT + i];
            s = fmaf(c, c, s);
        }
        g_csq[i] = s;
    }
    if (i == 0) { g_loss = 0.0f; g_done = 0u; }
}

// ---------------------------------------------------------------------------
// Assignment: per-row argmax_k (2*x.c_k - csq[k])  == argmin distance.
// (R2 kernel verbatim — measured at the FFMA2 rt=3 RF-bank roofline.)
// ---------------------------------------------------------------------------
__global__ void __launch_bounds__(256, 2)
assign_kernel(const float* __restrict__ X, const float* __restrict__ C) {
    extern __shared__ float smem[];
    float* xs = smem;                 // [64][132] x tile, transposed: xs[d][r]
    float* cs = smem + 64 * 132;      // [64][132] C chunk: cs[d][c]
    int*   s_ind = (int*)(smem + 2 * 64 * 132);   // [128]

    const int tid = threadIdx.x;
    const int tx = tid & 15;
    const int ty = tid >> 4;
    const int rb = blockIdx.x * 128;

    // Load x tile [128 rows x 64] transposed into smem
    const float4* Xv = reinterpret_cast<const float4*>(X + (size_t)rb * DIM);
    #pragma unroll
    for (int f = tid; f < 2048; f += 256) {
        float4 v = Xv[f];
        int r = f >> 4;
        int d = (f & 15) * 4;
        xs[(d + 0) * 132 + r] = v.x;
        xs[(d + 1) * 132 + r] = v.y;
        xs[(d + 2) * 132 + r] = v.z;
        xs[(d + 3) * 132 + r] = v.w;
    }

    float bestv[8];
    int   besti[8];
    #pragma unroll
    for (int i = 0; i < 8; i++) { bestv[i] = -3.402823466e38f; besti[i] = 0; }

    const int r0 = ty * 4;   // rows r0..r0+3 and 64+r0..64+r0+3
    const int c0 = tx * 4;   // cols c0..c0+3 and 64+c0..64+c0+3 (within chunk)

    for (int kc = 0; kc < 8; kc++) {
        __syncthreads();
        // Load C chunk [64 x 128], float4, coalesced
        #pragma unroll
        for (int f = tid; f < 2048; f += 256) {
            int d  = f >> 5;
            int c4 = f & 31;
            float4 v = *reinterpret_cast<const float4*>(C + d * KCENT + kc * 128 + c4 * 4);
            *reinterpret_cast<float4*>(&cs[d * 132 + c4 * 4]) = v;
        }
        __syncthreads();

        // accp[i][jj]: row i (8), packed column pair jj (4): cols 2jj, 2jj+1
        u64 accp[8][4];
        #pragma unroll
        for (int i = 0; i < 8; i++)
            #pragma unroll
            for (int jj = 0; jj < 4; jj++) accp[i][jj] = 0ULL;

        #pragma unroll 4
        for (int d = 0; d < 64; d++) {
            float4 a0 = *reinterpret_cast<const float4*>(&xs[d * 132 + r0]);
            float4 a1 = *reinterpret_cast<const float4*>(&xs[d * 132 + 64 + r0]);
            float4 b0 = *reinterpret_cast<const float4*>(&cs[d * 132 + c0]);
            float4 b1 = *reinterpret_cast<const float4*>(&cs[d * 132 + 64 + c0]);
            u64 bp[4];
            bp[0] = pack2(b0.x, b0.y);
            bp[1] = pack2(b0.z, b0.w);
            bp[2] = pack2(b1.x, b1.y);
            bp[3] = pack2(b1.z, b1.w);
            float a[8] = {a0.x, a0.y, a0.z, a0.w, a1.x, a1.y, a1.z, a1.w};
            #pragma unroll
            for (int i = 0; i < 8; i++) {
                u64 ad = pack2(a[i], a[i]);
                #pragma unroll
                for (int jj = 0; jj < 4; jj++)
                    accp[i][jj] = ffma2(ad, bp[jj], accp[i][jj]);
            }
        }

        // Epilogue: score = 2*dot - csq; running argmax, visiting columns in
        // ascending order per thread (strict > preserves first-min tiebreak)
        #pragma unroll
        for (int jj = 0; jj < 4; jj++) {
            int base = kc * 128 + ((jj < 2) ? (c0 + jj * 2) : (64 + c0 + (jj - 2) * 2));
            float cq0 = g_csq[base];
            float cq1 = g_csq[base + 1];
            #pragma unroll
            for (int i = 0; i < 8; i++) {
                float lo, hi;
                unpack2(accp[i][jj], lo, hi);
                float s0 = fmaf(2.0f, lo, -cq0);
                float s1 = fmaf(2.0f, hi, -cq1);
                if (s0 > bestv[i]) { bestv[i] = s0; besti[i] = base; }
                if (s1 > bestv[i]) { bestv[i] = s1; besti[i] = base + 1; }
            }
        }
    }

    // Reduce across the 16 tx-threads sharing each row group (half-warp xor).
    #pragma unroll
    for (int i = 0; i < 8; i++) {
        float v = bestv[i];
        int  ix = besti[i];
        #pragma unroll
        for (int off = 8; off > 0; off >>= 1) {
            float ov = __shfl_xor_sync(0xffffffffu, v, off);
            int   oi = __shfl_xor_sync(0xffffffffu, ix, off);
            if (ov > v || (ov == v && oi < ix)) { v = ov; ix = oi; }
        }
        if (tx == 0) {
            int row = (i < 4) ? (r0 + i) : (64 + r0 + (i - 4));
            s_ind[row] = ix;
        }
    }
    __syncthreads();

    // Fused segment sums: each warp handles 16 rows; lanes cover d and d+32.
    const int lane = tid & 31;
    const int w    = tid >> 5;
    #pragma unroll
    for (int t = 0; t < 16; t++) {
        int row = w * 16 + t;
        int k = s_ind[row];
        if (lane == 0) {
            g_ind[rb + row] = k;
            atomicAdd(&g_counts[k], 1);
        }
        atomicAdd(&g_csum[k * 64 + lane],      xs[lane * 132 + row]);
        atomicAdd(&g_csum[k * 64 + 32 + lane], xs[(32 + lane) * 132 + row]);
    }
}

// ---------------------------------------------------------------------------
// EMA update + Laplace smoothing + codebook normalize — fully parallel.
// ---------------------------------------------------------------------------
__global__ void update2_kernel(const float* __restrict__ cluster_size,
                               const float* __restrict__ cavg) {
    __shared__ float red[256];
    const int t = threadIdx.x;
    float s = cluster_size[t] + cluster_size[t + 256]
            + cluster_size[t + 512] + cluster_size[t + 768];
    red[t] = s;
    __syncthreads();
    #pragma unroll
    for (int st = 128; st > 0; st >>= 1) {
        if (t < st) red[t] += red[t + st];
        __syncthreads();
    }
    float n = 0.99f * red[0] + 0.01f * (float)N_PTS;

    int i = blockIdx.x * blockDim.x + t;   // 65536 threads
    int k = i >> 6;
    int d = i & 63;
    float csz = 0.99f * cluster_size[k] + 0.01f * (float)g_counts[k];
    float cs = (csz + 1e-5f) / (n + (float)KCENT * 1e-5f) * n;
    float avg_new = 0.99f * cavg[d * KCENT + k] + 0.01f * g_csum[i];
    g_cnew[i] = avg_new / cs;
}

// ---------------------------------------------------------------------------
// Gather + loss + fused finalize. 2048 blocks x 256 threads, 4 float4/thread
// handled as explicitly independent chains (max MLP), warp-shuffle reduction.
// ---------------------------------------------------------------------------
#define GATHER_BLOCKS 2048
#define GSTRIDE (GATHER_BLOCKS * 256)     // 524288 threads, x4 = N*D/4 float4s

__global__ void __launch_bounds__(256)
gather_kernel(const float* __restrict__ X, float* __restrict__ out, int out_size) {
    const int t0 = blockIdx.x * blockDim.x + threadIdx.x;
    const float4* Xv = reinterpret_cast<const float4*>(X);
    float4* Ov = reinterpret_cast<float4*>(out);

    // 4 independent element chains: load everything, then write everything
    int   idx[4];
    float4 xv[4], qv[4];
    #pragma unroll
    for (int j = 0; j < 4; j++) {
        int i = t0 + j * GSTRIDE;
        idx[j] = i;
        int n  = i >> 4;
        int d4 = (i & 15) * 4;
        int k  = g_ind[n];
        qv[j] = *reinterpret_cast<const float4*>(&g_cnew[k * 64 + d4]);
        xv[j] = Xv[i];
    }

    float lsum = 0.0f;
    #pragma unroll
    for (int j = 0; j < 4; j++) {
        float4 x = xv[j], q = qv[j];
        float4 o;
        o.x = x.x + (q.x - x.x);
        o.y = x.y + (q.y - x.y);
        o.z = x.z + (q.z - x.z);
        o.w = x.w + (q.w - x.w);
        Ov[idx[j]] = o;
        float dx = x.x - q.x, dy = x.y - q.y, dz = x.z - q.z, dw = x.w - q.w;
        lsum = fmaf(dx, dx, lsum);
        lsum = fmaf(dy, dy, lsum);
        lsum = fmaf(dz, dz, lsum);
        lsum = fmaf(dw, dw, lsum);
    }

    // warp shuffle reduce, then one smem round across 8 warps
    #pragma unroll
    for (int off = 16; off > 0; off >>= 1)
        lsum += __shfl_xor_sync(0xffffffffu, lsum, off);

    __shared__ float wsum[8];
    const int lane = threadIdx.x & 31;
    const int w    = threadIdx.x >> 5;
    if (lane == 0) wsum[w] = lsum;
    __syncthreads();
    if (threadIdx.x == 0) {
        float bs = wsum[0] + wsum[1] + wsum[2] + wsum[3]
                 + wsum[4] + wsum[5] + wsum[6] + wsum[7];
        atomicAdd(&g_loss, bs);
        __threadfence();
        unsigned int ticket = atomicAdd(&g_done, 1u);
        if (ticket == gridDim.x - 1) {
            float loss = g_loss * (1.0f / 8388608.0f);   // 1/(N*D), exact
            for (int j = N_PTS * DIM; j < out_size; j++) out[j] = loss;
        }
    }
}

// ---------------------------------------------------------------------------
extern "C" void kernel_launch(void* const* d_in, const int* in_sizes, int n_in,
                              void* d_out, int out_size) {
    const float* x             = (const float*)d_in[0];  // [N, D]
    const float* centroids     = (const float*)d_in[1];  // [D, K]
    const float* cluster_size  = (const float*)d_in[2];  // [K]
    const float* centroids_avg = (const float*)d_in[3];  // [D, K]
    float* out = (float*)d_out;

    const int smem_bytes = (2 * 64 * 132 + 128) * (int)sizeof(float);  // 68096
    cudaFuncSetAttribute(assign_kernel,
                         cudaFuncAttributeMaxDynamicSharedMemorySize, smem_bytes);

    prep_kernel<<<KCENT * DIM / 256, 256>>>(centroids);
    assign_kernel<<<N_PTS / 128, 256, smem_bytes>>>(x, centroids);
    update2_kernel<<<KCENT * DIM / 256, 256>>>(cluster_size, centroids_avg);
    gather_kernel<<<GATHER_BLOCKS, 256>>>(x, out, out_size);
}

// round 14
// speedup vs baseline: 1.0505x; 1.0505x over previous
#include <cuda_runtime.h>
#include <cstdint>

// Problem constants
#define N_PTS 131072
#define DIM   64
#define KCENT 1024

typedef unsigned long long u64;

// Scratch (device globals — no allocation allowed)
__device__ float g_csq[KCENT];
__device__ int   g_ind[N_PTS];
__device__ int   g_counts[KCENT];
__device__ float g_csum[KCENT * DIM];   // [k][d] segment sums of x
__device__ float g_cnew[KCENT * DIM];   // [k][d] updated codebook
__device__ float g_loss;
__device__ unsigned int g_done;

// ---- packed f32x2 helpers (Blackwell 2-wide fp32 datapath) ------------------
__device__ __forceinline__ u64 ffma2(u64 a, u64 b, u64 c) {
    u64 d;
    asm("fma.rn.f32x2 %0, %1, %2, %3;" : "=l"(d) : "l"(a), "l"(b), "l"(c));
    return d;
}
__device__ __forceinline__ u64 pack2(float lo, float hi) {
    u64 d; asm("mov.b64 %0, {%1, %2};" : "=l"(d) : "f"(lo), "f"(hi)); return d;
}
__device__ __forceinline__ void unpack2(u64 v, float& lo, float& hi) {
    asm("mov.b64 {%0, %1}, %2;" : "=f"(lo), "=f"(hi) : "l"(v));
}

// ---------------------------------------------------------------------------
// Fused prep: zero csum/counts/loss/done + csq[k] = sum_d C[d][k]^2
// grid 256 x 256 = 65536 threads (exactly KCENT*DIM)
// ---------------------------------------------------------------------------
__global__ void prep_kernel(const float* __restrict__ C) {
    int i = blockIdx.x * blockDim.x + threadIdx.x;
    g_csum[i] = 0.0f;
    if (i < KCENT) {
        g_counts[i] = 0;
        float s = 0.0f;
        #pragma unroll
        for (int d = 0; d < DIM; d++) {
            float c = C[d * KCENT + i];
            s = fmaf(c, c, s);
        }
        g_csq[i] = s;
    }
    if (i == 0) { g_loss = 0.0f; g_done = 0u; }
}

// ---------------------------------------------------------------------------
// Assignment: per-row argmax_k (2*x.c_k - csq[k])  == argmin distance.
// 128-row x-tile per block, loops K in 8 chunks of 128 columns.
// 256 threads, 8x8 register microtile done as 8x4 packed f32x2 accumulators.
// (R2/R11 kernel verbatim — measured at the FFMA2 rt=3 RF-bank roofline.)
// ---------------------------------------------------------------------------
__global__ void __launch_bounds__(256, 2)
assign_kernel(const float* __restrict__ X, const float* __restrict__ C) {
    extern __shared__ float smem[];
    float* xs = smem;                 // [64][132] x tile, transposed: xs[d][r]
    float* cs = smem + 64 * 132;      // [64][132] C chunk: cs[d][c]
    int*   s_ind = (int*)(smem + 2 * 64 * 132);   // [128]

    const int tid = threadIdx.x;
    const int tx = tid & 15;
    const int ty = tid >> 4;
    const int rb = blockIdx.x * 128;

    // Load x tile [128 rows x 64] transposed into smem
    const float4* Xv = reinterpret_cast<const float4*>(X + (size_t)rb * DIM);
    #pragma unroll
    for (int f = tid; f < 2048; f += 256) {
        float4 v = Xv[f];
        int r = f >> 4;
        int d = (f & 15) * 4;
        xs[(d + 0) * 132 + r] = v.x;
        xs[(d + 1) * 132 + r] = v.y;
        xs[(d + 2) * 132 + r] = v.z;
        xs[(d + 3) * 132 + r] = v.w;
    }

    float bestv[8];
    int   besti[8];
    #pragma unroll
    for (int i = 0; i < 8; i++) { bestv[i] = -3.402823466e38f; besti[i] = 0; }

    const int r0 = ty * 4;   // rows r0..r0+3 and 64+r0..64+r0+3
    const int c0 = tx * 4;   // cols c0..c0+3 and 64+c0..64+c0+3 (within chunk)

    for (int kc = 0; kc < 8; kc++) {
        __syncthreads();
        // Load C chunk [64 x 128], float4, coalesced
        #pragma unroll
        for (int f = tid; f < 2048; f += 256) {
            int d  = f >> 5;
            int c4 = f & 31;
            float4 v = *reinterpret_cast<const float4*>(C + d * KCENT + kc * 128 + c4 * 4);
            *reinterpret_cast<float4*>(&cs[d * 132 + c4 * 4]) = v;
        }
        __syncthreads();

        // accp[i][jj]: row i (8), packed column pair jj (4): cols 2jj, 2jj+1
        u64 accp[8][4];
        #pragma unroll
        for (int i = 0; i < 8; i++)
            #pragma unroll
            for (int jj = 0; jj < 4; jj++) accp[i][jj] = 0ULL;

        #pragma unroll 4
        for (int d = 0; d < 64; d++) {
            float4 a0 = *reinterpret_cast<const float4*>(&xs[d * 132 + r0]);
            float4 a1 = *reinterpret_cast<const float4*>(&xs[d * 132 + 64 + r0]);
            float4 b0 = *reinterpret_cast<const float4*>(&cs[d * 132 + c0]);
            float4 b1 = *reinterpret_cast<const float4*>(&cs[d * 132 + 64 + c0]);
            u64 bp[4];
            bp[0] = pack2(b0.x, b0.y);
            bp[1] = pack2(b0.z, b0.w);
            bp[2] = pack2(b1.x, b1.y);
            bp[3] = pack2(b1.z, b1.w);
            float a[8] = {a0.x, a0.y, a0.z, a0.w, a1.x, a1.y, a1.z, a1.w};
            #pragma unroll
            for (int i = 0; i < 8; i++) {
                u64 ad = pack2(a[i], a[i]);
                #pragma unroll
                for (int jj = 0; jj < 4; jj++)
                    accp[i][jj] = ffma2(ad, bp[jj], accp[i][jj]);
            }
        }

        // Epilogue: score = 2*dot - csq; running argmax, visiting columns in
        // ascending order per thread (strict > preserves first-min tiebreak)
        #pragma unroll
        for (int jj = 0; jj < 4; jj++) {
            int base = kc * 128 + ((jj < 2) ? (c0 + jj * 2) : (64 + c0 + (jj - 2) * 2));
            float cq0 = g_csq[base];
            float cq1 = g_csq[base + 1];
            #pragma unroll
            for (int i = 0; i < 8; i++) {
                float lo, hi;
                unpack2(accp[i][jj], lo, hi);
                float s0 = fmaf(2.0f, lo, -cq0);
                float s1 = fmaf(2.0f, hi, -cq1);
                if (s0 > bestv[i]) { bestv[i] = s0; besti[i] = base; }
                if (s1 > bestv[i]) { bestv[i] = s1; besti[i] = base + 1; }
            }
        }
    }

    // Reduce across the 16 tx-threads sharing each row group (half-warp xor).
    #pragma unroll
    for (int i = 0; i < 8; i++) {
        float v = bestv[i];
        int  ix = besti[i];
        #pragma unroll
        for (int off = 8; off > 0; off >>= 1) {
            float ov = __shfl_xor_sync(0xffffffffu, v, off);
            int   oi = __shfl_xor_sync(0xffffffffu, ix, off);
            if (ov > v || (ov == v && oi < ix)) { v = ov; ix = oi; }
        }
        if (tx == 0) {
            int row = (i < 4) ? (r0 + i) : (64 + r0 + (i - 4));
            s_ind[row] = ix;
        }
    }
    __syncthreads();

    // Fused segment sums: each warp handles 16 rows; lanes cover d and d+32.
    const int lane = tid & 31;
    const int w    = tid >> 5;
    #pragma unroll
    for (int t = 0; t < 16; t++) {
        int row = w * 16 + t;
        int k = s_ind[row];
        if (lane == 0) {
            g_ind[rb + row] = k;
            atomicAdd(&g_counts[k], 1);
        }
        atomicAdd(&g_csum[k * 64 + lane],      xs[lane * 132 + row]);
        atomicAdd(&g_csum[k * 64 + 32 + lane], xs[(32 + lane) * 132 + row]);
    }
}

// ---------------------------------------------------------------------------
// EMA update + Laplace smoothing + codebook normalize — fully parallel.
// Per-block reduction of cluster_size (4 KB, L2-resident) gives n.
// ---------------------------------------------------------------------------
__global__ void update2_kernel(const float* __restrict__ cluster_size,
                               const float* __restrict__ cavg) {
    __shared__ float red[256];
    const int t = threadIdx.x;
    float s = cluster_size[t] + cluster_size[t + 256]
            + cluster_size[t + 512] + cluster_size[t + 768];
    red[t] = s;
    __syncthreads();
    #pragma unroll
    for (int st = 128; st > 0; st >>= 1) {
        if (t < st) red[t] += red[t + st];
        __syncthreads();
    }
    float n = 0.99f * red[0] + 0.01f * (float)N_PTS;

    int i = blockIdx.x * blockDim.x + t;   // 65536 threads
    int k = i >> 6;
    int d = i & 63;
    float csz = 0.99f * cluster_size[k] + 0.01f * (float)g_counts[k];
    float cs = (csz + 1e-5f) / (n + (float)KCENT * 1e-5f) * n;
    float avg_new = 0.99f * cavg[d * KCENT + k] + 0.01f * g_csum[i];
    g_cnew[i] = avg_new / cs;
}

// ---------------------------------------------------------------------------
// Gather quantized vectors + loss (R11 shape: 2048 blocks, stride loop,
// smem tree reduction — measured 14.4us) + fused finalize via ticket.
// ---------------------------------------------------------------------------
__global__ void __launch_bounds__(256)
gather_kernel(const float* __restrict__ X, float* __restrict__ out, int out_size) {
    float lsum = 0.0f;
    const int stride = gridDim.x * blockDim.x;
    const float4* Xv = reinterpret_cast<const float4*>(X);
    float4* Ov = reinterpret_cast<float4*>(out);
    for (int i = blockIdx.x * blockDim.x + threadIdx.x; i < N_PTS * DIM / 4; i += stride) {
        int n  = i >> 4;
        int d4 = (i & 15) * 4;
        float4 q = *reinterpret_cast<const float4*>(&g_cnew[g_ind[n] * 64 + d4]);
        float4 x = Xv[i];
        float4 o;
        o.x = x.x + (q.x - x.x);
        o.y = x.y + (q.y - x.y);
        o.z = x.z + (q.z - x.z);
        o.w = x.w + (q.w - x.w);
        Ov[i] = o;
        float dx = x.x - q.x, dy = x.y - q.y, dz = x.z - q.z, dw = x.w - q.w;
        lsum = fmaf(dx, dx, lsum);
        lsum = fmaf(dy, dy, lsum);
        lsum = fmaf(dz, dz, lsum);
        lsum = fmaf(dw, dw, lsum);
    }
    __shared__ float red[256];
    red[threadIdx.x] = lsum;
    __syncthreads();
    #pragma unroll
    for (int s = 128; s > 0; s >>= 1) {
        if (threadIdx.x < s) red[threadIdx.x] += red[threadIdx.x + s];
        __syncthreads();
    }
    if (threadIdx.x == 0) {
        atomicAdd(&g_loss, red[0]);
        __threadfence();
        unsigned int ticket = atomicAdd(&g_done, 1u);
        if (ticket == gridDim.x - 1) {
            // all blocks' g_loss contributions are visible now
            float loss = g_loss * (1.0f / 8388608.0f);   // 1/(N*D), exact
            for (int j = N_PTS * DIM; j < out_size; j++) out[j] = loss;
        }
    }
}

// ---------------------------------------------------------------------------
extern "C" void kernel_launch(void* const* d_in, const int* in_sizes, int n_in,
                              void* d_out, int out_size) {
    const float* x             = (const float*)d_in[0];  // [N, D]
    const float* centroids     = (const float*)d_in[1];  // [D, K]
    const float* cluster_size  = (const float*)d_in[2];  // [K]
    const float* centroids_avg = (const float*)d_in[3];  // [D, K]
    float* out = (float*)d_out;

    const int smem_bytes = (2 * 64 * 132 + 128) * (int)sizeof(float);  // 68096
    cudaFuncSetAttribute(assign_kernel,
                         cudaFuncAttributeMaxDynamicSharedMemorySize, smem_bytes);

    prep_kernel<<<KCENT * DIM / 256, 256>>>(centroids);
    assign_kernel<<<N_PTS / 128, 256, smem_bytes>>>(x, centroids);
    update2_kernel<<<KCENT * DIM / 256, 256>>>(cluster_size, centroids_avg);
    gather_kernel<<<2048, 256>>>(x, out, out_size);
}

// round 15
// speedup vs baseline: 1.0523x; 1.0016x over previous
#include <cuda_runtime.h>
#include <cstdint>

// Problem constants
#define N_PTS 131072
#define DIM   64
#define KCENT 1024

typedef unsigned long long u64;

// Scratch (device globals — no allocation allowed)
__device__ float g_csq[KCENT];
__device__ int   g_ind[N_PTS];
__device__ int   g_counts[KCENT];
__device__ float g_csum[KCENT * DIM];   // [k][d] segment sums of x
__device__ float g_cnew[KCENT * DIM];   // [k][d] updated codebook
__device__ float g_loss;

// ---- packed f32x2 helpers (Blackwell 2-wide fp32 datapath) ------------------
__device__ __forceinline__ u64 ffma2(u64 a, u64 b, u64 c) {
    u64 d;
    asm("fma.rn.f32x2 %0, %1, %2, %3;" : "=l"(d) : "l"(a), "l"(b), "l"(c));
    return d;
}
__device__ __forceinline__ u64 pack2(float lo, float hi) {
    u64 d; asm("mov.b64 %0, {%1, %2};" : "=l"(d) : "f"(lo), "f"(hi)); return d;
}
__device__ __forceinline__ void unpack2(u64 v, float& lo, float& hi) {
    asm("mov.b64 {%0, %1}, %2;" : "=f"(lo), "=f"(hi) : "l"(v));
}

// ---------------------------------------------------------------------------
// Fused prep: zero csum/counts/loss + csq[k] = sum_d C[d][k]^2
// grid 256 x 256 = 65536 threads (exactly KCENT*DIM)
// ---------------------------------------------------------------------------
__global__ void prep_kernel(const float* __restrict__ C) {
    int i = blockIdx.x * blockDim.x + threadIdx.x;
    g_csum[i] = 0.0f;
    if (i < KCENT) {
        g_counts[i] = 0;
        float s = 0.0f;
        #pragma unroll
        for (int d = 0; d < DIM; d++) {
            float c = C[d * KCENT + i];
            s = fmaf(c, c, s);
        }
        g_csq[i] = s;
    }
    if (i == 0) g_loss = 0.0f;
}

// ---------------------------------------------------------------------------
// Assignment: per-row argmax_k (2*x.c_k - csq[k])  == argmin distance.
// 128-row x-tile per block, loops K in 8 chunks of 128 columns.
// 256 threads, 8x8 register microtile done as 8x4 packed f32x2 accumulators.
// Epilogue: half-warp argmax reduction, then fused segment-sum atomics.
// (Measured at the FFMA2 rt=3 RF-bank roofline: fma busy ~2/3, issue ~1/2.)
// ---------------------------------------------------------------------------
__global__ void __launch_bounds__(256, 2)
assign_kernel(const float* __restrict__ X, const float* __restrict__ C) {
    extern __shared__ float smem[];
    float* xs = smem;                 // [64][132] x tile, transposed: xs[d][r]
    float* cs = smem + 64 * 132;      // [64][132] C chunk: cs[d][c]
    int*   s_ind = (int*)(smem + 2 * 64 * 132);   // [128]

    const int tid = threadIdx.x;
    const int tx = tid & 15;
    const int ty = tid >> 4;
    const int rb = blockIdx.x * 128;

    // Load x tile [128 rows x 64] transposed into smem
    const float4* Xv = reinterpret_cast<const float4*>(X + (size_t)rb * DIM);
    #pragma unroll
    for (int f = tid; f < 2048; f += 256) {
        float4 v = Xv[f];
        int r = f >> 4;
        int d = (f & 15) * 4;
        xs[(d + 0) * 132 + r] = v.x;
        xs[(d + 1) * 132 + r] = v.y;
        xs[(d + 2) * 132 + r] = v.z;
        xs[(d + 3) * 132 + r] = v.w;
    }

    float bestv[8];
    int   besti[8];
    #pragma unroll
    for (int i = 0; i < 8; i++) { bestv[i] = -3.402823466e38f; besti[i] = 0; }

    const int r0 = ty * 4;   // rows r0..r0+3 and 64+r0..64+r0+3
    const int c0 = tx * 4;   // cols c0..c0+3 and 64+c0..64+c0+3 (within chunk)

    for (int kc = 0; kc < 8; kc++) {
        __syncthreads();
        // Load C chunk [64 x 128], float4, coalesced
        #pragma unroll
        for (int f = tid; f < 2048; f += 256) {
            int d  = f >> 5;
            int c4 = f & 31;
            float4 v = *reinterpret_cast<const float4*>(C + d * KCENT + kc * 128 + c4 * 4);
            *reinterpret_cast<float4*>(&cs[d * 132 + c4 * 4]) = v;
        }
        __syncthreads();

        // accp[i][jj]: row i (8), packed column pair jj (4): cols 2jj, 2jj+1
        u64 accp[8][4];
        #pragma unroll
        for (int i = 0; i < 8; i++)
            #pragma unroll
            for (int jj = 0; jj < 4; jj++) accp[i][jj] = 0ULL;

        #pragma unroll 4
        for (int d = 0; d < 64; d++) {
            float4 a0 = *reinterpret_cast<const float4*>(&xs[d * 132 + r0]);
            float4 a1 = *reinterpret_cast<const float4*>(&xs[d * 132 + 64 + r0]);
            float4 b0 = *reinterpret_cast<const float4*>(&cs[d * 132 + c0]);
            float4 b1 = *reinterpret_cast<const float4*>(&cs[d * 132 + 64 + c0]);
            u64 bp[4];
            bp[0] = pack2(b0.x, b0.y);
            bp[1] = pack2(b0.z, b0.w);
            bp[2] = pack2(b1.x, b1.y);
            bp[3] = pack2(b1.z, b1.w);
            float a[8] = {a0.x, a0.y, a0.z, a0.w, a1.x, a1.y, a1.z, a1.w};
            #pragma unroll
            for (int i = 0; i < 8; i++) {
                u64 ad = pack2(a[i], a[i]);
                #pragma unroll
                for (int jj = 0; jj < 4; jj++)
                    accp[i][jj] = ffma2(ad, bp[jj], accp[i][jj]);
            }
        }

        // Epilogue: score = 2*dot - csq; running argmax, visiting columns in
        // ascending order per thread (strict > preserves first-min tiebreak)
        #pragma unroll
        for (int jj = 0; jj < 4; jj++) {
            int base = kc * 128 + ((jj < 2) ? (c0 + jj * 2) : (64 + c0 + (jj - 2) * 2));
            float cq0 = g_csq[base];
            float cq1 = g_csq[base + 1];
            #pragma unroll
            for (int i = 0; i < 8; i++) {
                float lo, hi;
                unpack2(accp[i][jj], lo, hi);
                float s0 = fmaf(2.0f, lo, -cq0);
                float s1 = fmaf(2.0f, hi, -cq1);
                if (s0 > bestv[i]) { bestv[i] = s0; besti[i] = base; }
                if (s1 > bestv[i]) { bestv[i] = s1; besti[i] = base + 1; }
            }
        }
    }

    // Reduce across the 16 tx-threads sharing each row group (half-warp xor).
    #pragma unroll
    for (int i = 0; i < 8; i++) {
        float v = bestv[i];
        int  ix = besti[i];
        #pragma unroll
        for (int off = 8; off > 0; off >>= 1) {
            float ov = __shfl_xor_sync(0xffffffffu, v, off);
            int   oi = __shfl_xor_sync(0xffffffffu, ix, off);
            if (ov > v || (ov == v && oi < ix)) { v = ov; ix = oi; }
        }
        if (tx == 0) {
            int row = (i < 4) ? (r0 + i) : (64 + r0 + (i - 4));
            s_ind[row] = ix;
        }
    }
    __syncthreads();

    // Fused segment sums: each warp handles 16 rows; lanes cover d and d+32.
    const int lane = tid & 31;
    const int w    = tid >> 5;
    #pragma unroll
    for (int t = 0; t < 16; t++) {
        int row = w * 16 + t;
        int k = s_ind[row];
        if (lane == 0) {
            g_ind[rb + row] = k;
            atomicAdd(&g_counts[k], 1);
        }
        atomicAdd(&g_csum[k * 64 + lane],      xs[lane * 132 + row]);
        atomicAdd(&g_csum[k * 64 + 32 + lane], xs[(32 + lane) * 132 + row]);
    }
}

// ---------------------------------------------------------------------------
// EMA update + Laplace smoothing + codebook normalize — fully parallel.
// Per-block reduction of cluster_size (4 KB, L2-resident) gives n.
// ---------------------------------------------------------------------------
__global__ void update2_kernel(const float* __restrict__ cluster_size,
                               const float* __restrict__ cavg) {
    __shared__ float red[256];
    const int t = threadIdx.x;
    float s = cluster_size[t] + cluster_size[t + 256]
            + cluster_size[t + 512] + cluster_size[t + 768];
    red[t] = s;
    __syncthreads();
    #pragma unroll
    for (int st = 128; st > 0; st >>= 1) {
        if (t < st) red[t] += red[t + st];
        __syncthreads();
    }
    float n = 0.99f * red[0] + 0.01f * (float)N_PTS;

    int i = blockIdx.x * blockDim.x + t;   // 65536 threads
    int k = i >> 6;
    int d = i & 63;
    float csz = 0.99f * cluster_size[k] + 0.01f * (float)g_counts[k];
    float cs = (csz + 1e-5f) / (n + (float)KCENT * 1e-5f) * n;
    float avg_new = 0.99f * cavg[d * KCENT + k] + 0.01f * g_csum[i];
    g_cnew[i] = avg_new / cs;
}

// ---------------------------------------------------------------------------
// Gather quantized vectors + loss partial sums (float4 vectorized).
// ---------------------------------------------------------------------------
__global__ void gather_kernel(const float* __restrict__ X, float* __restrict__ out) {
    float lsum = 0.0f;
    const int stride = gridDim.x * blockDim.x;
    const float4* Xv = reinterpret_cast<const float4*>(X);
    float4* Ov = reinterpret_cast<float4*>(out);
    for (int i = blockIdx.x * blockDim.x + threadIdx.x; i < N_PTS * DIM / 4; i += stride) {
        int n  = i >> 4;
        int d4 = (i & 15) * 4;
        float4 q = *reinterpret_cast<const float4*>(&g_cnew[g_ind[n] * 64 + d4]);
        float4 x = Xv[i];
        float4 o;
        o.x = x.x + (q.x - x.x);
        o.y = x.y + (q.y - x.y);
        o.z = x.z + (q.z - x.z);
        o.w = x.w + (q.w - x.w);
        Ov[i] = o;
        float dx = x.x - q.x, dy = x.y - q.y, dz = x.z - q.z, dw = x.w - q.w;
        lsum = fmaf(dx, dx, lsum);
        lsum = fmaf(dy, dy, lsum);
        lsum = fmaf(dz, dz, lsum);
        lsum = fmaf(dw, dw, lsum);
    }
    __shared__ float red[256];
    red[threadIdx.x] = lsum;
    __syncthreads();
    #pragma unroll
    for (int s = 128; s > 0; s >>= 1) {
        if (threadIdx.x < s) red[threadIdx.x] += red[threadIdx.x + s];
        __syncthreads();
    }
    if (threadIdx.x == 0) atomicAdd(&g_loss, red[0]);
}

// Final scalar: mean loss into the tail of the output buffer (if present).
__global__ void finalize_kernel(float* out, int out_size) {
    float loss = g_loss * (1.0f / 8388608.0f);   // 1/(N*D), exact power of 2
    for (int i = N_PTS * DIM; i < out_size; i++) out[i] = loss;
}

// ---------------------------------------------------------------------------
extern "C" void kernel_launch(void* const* d_in, const int* in_sizes, int n_in,
                              void* d_out, int out_size) {
    const float* x             = (const float*)d_in[0];  // [N, D]
    const float* centroids     = (const float*)d_in[1];  // [D, K]
    const float* cluster_size  = (const float*)d_in[2];  // [K]
    const float* centroids_avg = (const float*)d_in[3];  // [D, K]
    float* out = (float*)d_out;

    const int smem_bytes = (2 * 64 * 132 + 128) * (int)sizeof(float);  // 68096
    cudaFuncSetAttribute(assign_kernel,
                         cudaFuncAttributeMaxDynamicSharedMemorySize, smem_bytes);

    prep_kernel<<<KCENT * DIM / 256, 256>>>(centroids);
    assign_kernel<<<N_PTS / 128, 256, smem_bytes>>>(x, centroids);
    update2_kernel<<<KCENT * DIM / 256, 256>>>(cluster_size, centroids_avg);
    gather_kernel<<<2048, 256>>>(x, out);
    finalize_kernel<<<1, 1>>>(out, out_size);
}